// round 7
// baseline (speedup 1.0000x reference)
#include <cuda_runtime.h>
#include <stdint.h>

// Instant-NGP hash grid encode — pair-fused, branch-free predicated loads.
// B=524288 points, D=3, L=16 levels, C=2, H=16, hashed table size 2^19.
//
// Evidence trail: L1tex wavefronts bind (~92% SOL). x-adjacent corner pairs
// fuse into one LDG.128 with prob 1/2 (even low index) after even-base table
// repack. R6's divergent pair_load cost ~16% per-wavefront throughput via
// BSSY serialization (MLP collapse). R7: uniform stream — unconditional
// LDG.128 of chunk(i0), single predicated LDG.128 of chunk(i1), half-select.

#define NPOINTS  524288
#define NLEVELS  16
#define NPAIRS   (NPOINTS * NLEVELS)

// src level offsets: 0,4913,40850,315475, then +524288 each
// dst (aligned) offsets: pad levels 0..2 by one entry so every base is even
#define TOTAL_DST 7131222

__device__ __align__(16) float2 g_emb[TOTAL_DST];

__constant__ int c_dst_off[16] = {
    0, 4914, 40852, 315478,
    839766, 1364054, 1888342, 2412630,
    2936918, 3461206, 3985494, 4509782,
    5034070, 5558358, 6082646, 6606934
};

__device__ __forceinline__ int repack_shift(int t) {
    return (t >= 315478) ? 3 : (t >= 40852) ? 2 : (t >= 4914) ? 1 : 0;
}

__global__ __launch_bounds__(256)
void repack_kernel(const float2* __restrict__ src)
{
    int t = (blockIdx.x * blockDim.x + threadIdx.x) * 2;  // TOTAL_DST is even
    if (t >= TOTAL_DST) return;
    float2 a = src[t     - repack_shift(t)];
    float2 b = src[t + 1 - repack_shift(t + 1)];
    *reinterpret_cast<float4*>(&g_emb[t]) = make_float4(a.x, a.y, b.x, b.y);
}

__global__ __launch_bounds__(256)
void hash_encode_kernel(const float* __restrict__ in,
                        float2* __restrict__ out)
{
    int tid = blockIdx.x * blockDim.x + threadIdx.x;
    if (tid >= NPAIRS) return;

    int b = tid >> 4;
    int l = tid & 15;

    // map [-1,1) -> [0,1)
    float x = (__ldg(&in[b * 3 + 0]) + 1.0f) * 0.5f;
    float y = (__ldg(&in[b * 3 + 1]) + 1.0f) * 0.5f;
    float z = (__ldg(&in[b * 3 + 2]) + 1.0f) * 0.5f;

    uint32_t res = 16u << l;
    float fres = (float)res;

    float px = x * fres, py = y * fres, pz = z * fres;
    float gx = floorf(px), gy = floorf(py), gz = floorf(pz);
    float fx = px - gx,   fy = py - gy,   fz = pz - gz;
    uint32_t ux = (uint32_t)gx, uy = (uint32_t)gy, uz = (uint32_t)gz;

    // hashed-form partials: idx = (ux*1 ^ uy*P1 ^ uz*P2) & (2^19 - 1)
    const uint32_t P1 = 2654435761u;
    const uint32_t P2 = 805459861u;
    uint32_t hx0 = ux;        uint32_t hx1 = ux + 1u;
    uint32_t hy0 = uy * P1;   uint32_t hy1 = hy0 + P1;
    uint32_t hz0 = uz * P2;   uint32_t hz1 = hz0 + P2;

    // dense-form partials: idx = ux + uy*(res+1) + uz*(res+1)^2 (in range,
    // x < 1 strictly). Garbage for hashed lanes; selected away below.
    uint32_t r1 = res + 1u;
    uint32_t r2 = r1 * r1;
    uint32_t sy0 = uy * r1;  uint32_t sy1 = sy0 + r1;
    uint32_t sz0 = uz * r2;  uint32_t sz1 = sz0 + r2;

    bool hashed = (l >= 3);
    const float2* __restrict__ tab = g_emb + c_dst_off[l];

    // Per pair p (p = ybit | zbit<<1): corners (x0,x1).
    // Uniform load scheme: always load 16B chunk of i0; predicated single
    // LDG.128 for chunk of i1 when different; select halves by idx&1.
    uint32_t ia[4], ib[4];
#pragma unroll
    for (int p = 0; p < 4; p++) {
        uint32_t hyz = ((p & 1) ? hy1 : hy0) ^ ((p & 2) ? hz1 : hz0);
        uint32_t ih0 = (hx0 ^ hyz) & 0x7FFFFu;
        uint32_t ih1 = (hx1 ^ hyz) & 0x7FFFFu;
        uint32_t s   = ((p & 1) ? sy1 : sy0) + ((p & 2) ? sz1 : sz0) + ux;
        ia[p] = hashed ? ih0 : s;
        ib[p] = hashed ? ih1 : (s + 1u);
    }

    float4 qa[4], qb[4];
#pragma unroll
    for (int p = 0; p < 4; p++) {
        const float4* c0 = reinterpret_cast<const float4*>(tab + (ia[p] & ~1u));
        const float4* c1 = reinterpret_cast<const float4*>(tab + (ib[p] & ~1u));
        qa[p] = __ldg(c0);
        qb[p] = qa[p];
        if (c1 != c0) qb[p] = __ldg(c1);   // single predicated LDG.128
    }

    // trilinear weights
    float wx[2] = {1.0f - fx, fx};
    float wy[2] = {1.0f - fy, fy};
    float wz[2] = {1.0f - fz, fz};

    float ax = 0.0f, ay = 0.0f;
#pragma unroll
    for (int p = 0; p < 4; p++) {
        float wyz = wy[p & 1] * wz[(p >> 1) & 1];
        float2 v0 = (ia[p] & 1u) ? make_float2(qa[p].z, qa[p].w)
                                 : make_float2(qa[p].x, qa[p].y);
        float2 v1 = (ib[p] & 1u) ? make_float2(qb[p].z, qb[p].w)
                                 : make_float2(qb[p].x, qb[p].y);
        float w0 = wx[0] * wyz;
        float w1 = wx[1] * wyz;
        ax = fmaf(w0, v0.x, ax);  ay = fmaf(w0, v0.y, ay);
        ax = fmaf(w1, v1.x, ax);  ay = fmaf(w1, v1.y, ay);
    }

    out[tid] = make_float2(ax, ay);
}

extern "C" void kernel_launch(void* const* d_in, const int* in_sizes, int n_in,
                              void* d_out, int out_size)
{
    const float*  inputs = (const float*)d_in[0];
    const float2* emb    = (const float2*)d_in[1];
    float2*       out    = (float2*)d_out;

    // 1) repack table into even-base (16B-aligned) layout. Idempotent,
    //    deterministic, graph-capturable.
    {
        int nthreads = TOTAL_DST / 2;
        repack_kernel<<<(nthreads + 255) / 256, 256>>>(emb);
    }

    // 2) gather/interpolate
    hash_encode_kernel<<<(NPAIRS + 255) / 256, 256>>>(inputs, out);
}